// round 15
// baseline (speedup 1.0000x reference)
#include <cuda_runtime.h>
#include <cuda_bf16.h>
#include <cstdint>

#define BB 4
#define CC 64
#define NN 8192
#define KNB 40
#define FFD 256
#define NPTS (BB*NN)
#define BCAP 32
#define BPITCH 33
#define CTILE 128
#define QTILE 64

// ---------------- scratch (device globals: no allocations allowed) ----------
__device__ float g_pcd[NPTS*CC];   // (B,N,C) transposed input
__device__ __nv_bfloat16 g_pch[NPTS*CC]; // bf16 hi split
__device__ __nv_bfloat16 g_pcl[NPTS*CC]; // bf16 lo split
__device__ float g_aa [NPTS];      // squared norms
__device__ float g_qp [NPTS*CC];   // pcd @ Wq^T
__device__ float g_kp [NPTS*CC];   // pcd @ Wk^T
__device__ float g_vp [NPTS*CC];   // pcd @ Wv^T
__device__ int   g_idx[NPTS*KNB];  // knn indices
__device__ float g_y1 [NPTS*CC];
__device__ float g_y2 [NPTS*CC];
__device__ float g_part[2*64*128];
__device__ float g_scb [2*128];

__device__ __forceinline__ uint32_t sm_u32(const void* p){
    uint32_t a;
    asm("{ .reg .u64 t; cvta.to.shared.u64 t, %1; cvt.u32.u64 %0, t; }":"=r"(a):"l"(p));
    return a;
}
__device__ __forceinline__ void cpa16(uint32_t dst, const void* src){
    asm volatile("cp.async.ca.shared.global [%0], [%1], 16;" :: "r"(dst), "l"(src));
}
#define CPA_COMMIT() asm volatile("cp.async.commit_group;" ::: "memory")
#define CPA_WAIT(n)  asm volatile("cp.async.wait_group %0;" :: "n"(n) : "memory")
__device__ __forceinline__ void ldm_x4(uint32_t& r0, uint32_t& r1, uint32_t& r2,
                                       uint32_t& r3, uint32_t addr){
    asm volatile("ldmatrix.sync.aligned.m8n8.x4.shared.b16 {%0,%1,%2,%3}, [%4];"
        : "=r"(r0), "=r"(r1), "=r"(r2), "=r"(r3) : "r"(addr));
}

// ---------------- K1: transpose x (B,C,N) -> pcd (B,N,C) --------------------
__global__ void k_transpose(const float* __restrict__ x){
    __shared__ float t[32][33];
    const int n0 = blockIdx.x*32, c0 = blockIdx.y*32, b = blockIdx.z;
    const float* xb = x + (size_t)b*CC*NN;
    #pragma unroll
    for (int i = threadIdx.y; i < 32; i += 8)
        t[i][threadIdx.x] = xb[(size_t)(c0+i)*NN + n0 + threadIdx.x];
    __syncthreads();
    float* pb = g_pcd + (size_t)b*NN*CC;
    #pragma unroll
    for (int i = threadIdx.y; i < 32; i += 8)
        pb[(size_t)(n0+i)*CC + c0 + threadIdx.x] = t[threadIdx.x][i];
}

// ---------------- K2 (merged): aa + bf16 hi/lo split (warp per point) -------
__global__ void k_prep(){
    const int p    = blockIdx.x*8 + (threadIdx.x>>5);
    const int lane = threadIdx.x & 31;
    const float* r = g_pcd + (size_t)p*CC;
    float v0 = r[lane], v1 = r[lane+32];
    __nv_bfloat16 h0 = __float2bfloat16(v0), h1 = __float2bfloat16(v1);
    g_pch[(size_t)p*CC + lane]      = h0;
    g_pch[(size_t)p*CC + lane + 32] = h1;
    g_pcl[(size_t)p*CC + lane]      = __float2bfloat16(v0 - __bfloat162float(h0));
    g_pcl[(size_t)p*CC + lane + 32] = __float2bfloat16(v1 - __bfloat162float(h1));
    float a = v0*v0 + v1*v1;
    #pragma unroll
    for (int o = 16; o; o >>= 1) a += __shfl_xor_sync(0xffffffffu, a, o);
    if (!lane) g_aa[p] = a;
}

// ---------------- K3: qp/kp/vp = pcd @ W^T (64-pt tiles) ---------------------
__global__ void __launch_bounds__(256) k_proj(const float* __restrict__ Wq,
                                              const float* __restrict__ Wk,
                                              const float* __restrict__ Wv){
    __shared__ float Pt[64*68];   // [k][p]
    __shared__ float Wt[64*68];   // [k][o]
    const int t  = threadIdx.x;
    const int r0 = blockIdx.x*64;
    for (int i = t; i < 64*64; i += 256){
        int p = i>>6, k = i&63;
        Pt[k*68+p] = g_pcd[(size_t)(r0+p)*CC + k];
    }
    const int tp = t & 15, to = t >> 4;
    const float* Ws[3] = {Wq, Wk, Wv};
    float* Os[3];
    Os[0] = g_qp; Os[1] = g_kp; Os[2] = g_vp;
    for (int m = 0; m < 3; m++){
        __syncthreads();
        const float* W = Ws[m];
        for (int i = t; i < 64*64; i += 256){
            int o = i>>6, k = i&63;
            Wt[k*68+o] = W[i];
        }
        __syncthreads();
        float acc[4][4];
        #pragma unroll
        for (int i=0;i<4;i++) { acc[i][0]=0.f; acc[i][1]=0.f; acc[i][2]=0.f; acc[i][3]=0.f; }
        #pragma unroll 8
        for (int kk = 0; kk < 64; kk++){
            float4 a = *(const float4*)&Pt[kk*68 + tp*4];
            float4 w = *(const float4*)&Wt[kk*68 + to*4];
            float av[4] = {a.x,a.y,a.z,a.w};
            float wv[4] = {w.x,w.y,w.z,w.w};
            #pragma unroll
            for (int i=0;i<4;i++)
                #pragma unroll
                for (int j=0;j<4;j++) acc[i][j] += av[i]*wv[j];
        }
        float* O = Os[m];
        #pragma unroll
        for (int i = 0; i < 4; i++){
            float4 v4 = make_float4(acc[i][0], acc[i][1], acc[i][2], acc[i][3]);
            *(float4*)&O[(size_t)(r0 + tp*4 + i)*CC + to*4] = v4;
        }
    }
}

// ---------------- K4: KNN, mma.sync bf16-split + ldmatrix, CTILE=128 --------
// smem bytes: Cbuf[2]@0 (each: CH 18432 + CL 18432) | fx@73728
// Q is staged transiently in Cbuf[0] and hoisted to registers.
#define PITCHB 144            // 72 bf16 per row
#define CB_OFF 0
#define CCOMP 18432           // one component (hi or lo) = 128 rows * 144 B
#define CBUF_SZ (2*CCOMP)
#define FX_OFF 73728
// fx floats: aq 64 | ac 256 | thr 64 | ld 2560 | bufv 2112 | li 2560 | bufi 2112 | cnt 64
#define KNN_SMEM (FX_OFF + 9792*4)

#define MMA_BF16(dd, a, b0_, b1_) \
    asm volatile("mma.sync.aligned.m16n8k16.row.col.f32.bf16.bf16.f32 " \
        "{%0,%1,%2,%3}, {%4,%5,%6,%7}, {%8,%9}, {%0,%1,%2,%3};" \
        : "+f"((dd)[0]), "+f"((dd)[1]), "+f"((dd)[2]), "+f"((dd)[3]) \
        : "r"((a)[0]), "r"((a)[1]), "r"((a)[2]), "r"((a)[3]), \
          "r"(b0_), "r"(b1_))

__global__ void __launch_bounds__(256,2) k_knn(){
    extern __shared__ char sm[];
    const uint32_t smb = sm_u32(sm);
    float* fx   = (float*)(sm + FX_OFF);
    float* aq   = fx;                  // 64
    float* ac   = fx + 64;             // 256 = 2 x 128
    float* thr  = fx + 320;            // 64
    float* ld   = fx + 384;            // 40*64
    float* bufv = fx + 2944;           // 64*33
    int*   li   = (int*)(fx + 5056);   // 40*64
    int*   bufi = (int*)(fx + 7616);   // 64*33
    int*   cnt  = (int*)(fx + 9728);   // 64

    const int b  = blockIdx.y;
    const int q0 = blockIdx.x*QTILE;
    const int t  = threadIdx.x;
    const int lane = t & 31;
    const int g  = lane >> 2;          // group row 0..7
    const int qq = lane & 3;           // quad col 0..3
    const int qb = ((t>>5) & 3)*16;    // warp's query base
    const int cb = (t>>7)*64;          // warp's candidate-col base (0 or 64)

    // ---- stage Q tiles transiently into Cbuf[0] (bf16 hi/lo) ----
    {
        const uint4* qh = (const uint4*)(g_pch + (size_t)(b*NN + q0)*CC);
        const uint4* ql = (const uint4*)(g_pcl + (size_t)(b*NN + q0)*CC);
        #pragma unroll
        for (int rep = 0; rep < 2; rep++){
            int i = t + rep*256;
            int row = i >> 3, c16 = i & 7;
            int off = row*PITCHB + c16*16;
            *(uint4*)(sm + off) = qh[i];
            *(uint4*)(sm + 9216 + off) = ql[i];
        }
    }
    if (t < QTILE){ aq[t] = g_aa[(size_t)b*NN + q0 + t]; thr[t] = -3.4e38f; cnt[t] = 0; }
    __syncthreads();   // Q staging visible

    // ---- hoist Q fragments into registers (constant across all tiles) ----
    uint32_t ahr[4][4], alr[4][4];
    #pragma unroll
    for (int kc = 0; kc < 4; kc++){
        const int koff = kc*32 + qq*4;
        int r0b = (qb + g)*PITCHB + koff;
        int r1b = r0b + 8*PITCHB;
        ahr[kc][0] = *(const uint32_t*)(sm + r0b);
        ahr[kc][1] = *(const uint32_t*)(sm + r1b);
        ahr[kc][2] = *(const uint32_t*)(sm + r0b + 16);
        ahr[kc][3] = *(const uint32_t*)(sm + r1b + 16);
        alr[kc][0] = *(const uint32_t*)(sm + 9216 + r0b);
        alr[kc][1] = *(const uint32_t*)(sm + 9216 + r1b);
        alr[kc][2] = *(const uint32_t*)(sm + 9216 + r0b + 16);
        alr[kc][3] = *(const uint32_t*)(sm + 9216 + r1b + 16);
    }
    __syncthreads();   // all Q reads done before cp.async overwrites Cbuf[0]

    // ---- cp.async prologue: tile 0 into buffer 0; ac[0] direct ----
    {
        const uint4* ch = (const uint4*)(g_pch + (size_t)(b*NN)*CC);
        const uint4* cl = (const uint4*)(g_pcl + (size_t)(b*NN)*CC);
        #pragma unroll
        for (int rep = 0; rep < 4; rep++){
            int i = t + rep*256;
            int row = i >> 3, c16 = i & 7;
            uint32_t off = row*PITCHB + c16*16;
            cpa16(smb + CB_OFF + off, ch + i);
            cpa16(smb + CB_OFF + CCOMP + off, cl + i);
        }
        CPA_COMMIT();
        if (t < CTILE) ac[t] = g_aa[(size_t)b*NN + t];
    }

    // ---- per-lane ldmatrix base ----
    const int lm = lane >> 3;
    const uint32_t matOff = (uint32_t)((cb + (lm>>1)*8 + (lane&7))*PITCHB + (lm&1)*16);

    float vmin = -3.4e38f;   // owner state (t<64 owns query t)
    int   minpos = 0;

    const int NT = NN/CTILE;   // 64
    for (int ct = 0; ct < NT; ct++){
        const int s = ct & 1;
        const int c0 = ct*CTILE;
        float na = 0.f;
        // ---- issue next tile into other buffer ----
        if (ct + 1 < NT){
            const int c0n = (ct+1)*CTILE;
            const uint4* ch = (const uint4*)(g_pch + (size_t)(b*NN + c0n)*CC);
            const uint4* cl = (const uint4*)(g_pcl + (size_t)(b*NN + c0n)*CC);
            const uint32_t cbase = smb + CB_OFF + (uint32_t)(s^1)*CBUF_SZ;
            #pragma unroll
            for (int rep = 0; rep < 4; rep++){
                int i = t + rep*256;
                int row = i >> 3, c16 = i & 7;
                uint32_t off = row*PITCHB + c16*16;
                cpa16(cbase + off, ch + i);
                cpa16(cbase + CCOMP + off, cl + i);
            }
            CPA_COMMIT();
            if (t < CTILE) na = g_aa[(size_t)b*NN + c0n + t];
            CPA_WAIT(1);
        } else {
            CPA_WAIT(0);
        }
        __syncthreads();      // barrier 1: tile ct data + prior insert state visible

        // ---- warp GEMM: 16q x 64c via m16n8k16 + ldmatrix, 3-term split ----
        const uint32_t chb = smb + CB_OFF + (uint32_t)s*CBUF_SZ + matOff;
        float d[8][4];
        #pragma unroll
        for (int ni=0;ni<8;ni++)
            #pragma unroll
            for (int j=0;j<4;j++) d[ni][j] = 0.f;

        #pragma unroll
        for (int kc = 0; kc < 4; kc++){
            const uint32_t ka = chb + kc*32;
            uint32_t bh[16], bl[16];
            #pragma unroll
            for (int grp = 0; grp < 4; grp++){
                ldm_x4(bh[grp*4], bh[grp*4+1], bh[grp*4+2], bh[grp*4+3],
                       ka + grp*16*PITCHB);
                ldm_x4(bl[grp*4], bl[grp*4+1], bl[grp*4+2], bl[grp*4+3],
                       ka + CCOMP + grp*16*PITCHB);
            }
            #pragma unroll
            for (int ni=0;ni<8;ni++){
                MMA_BF16(d[ni], ahr[kc], bh[ni*2], bh[ni*2+1]);
                MMA_BF16(d[ni], ahr[kc], bl[ni*2], bl[ni*2+1]);
                MMA_BF16(d[ni], alr[kc], bh[ni*2], bh[ni*2+1]);
            }
        }

        // ---- fold pd = 2*dot - aq - ac; per-thread vmax ----
        float vmax;
        {
            const float* acb = ac + s*128;
            float aq0 = aq[qb + g];
            float aq1 = aq[qb + g + 8];
            #pragma unroll
            for (int ni=0;ni<8;ni++){
                float ac0 = acb[cb + ni*8 + qq*2];
                float ac1 = acb[cb + ni*8 + qq*2 + 1];
                d[ni][0] = 2.f*d[ni][0] - aq0 - ac0;
                d[ni][1] = 2.f*d[ni][1] - aq0 - ac1;
                d[ni][2] = 2.f*d[ni][2] - aq1 - ac0;
                d[ni][3] = 2.f*d[ni][3] - aq1 - ac1;
            }
            vmax = d[0][0];
            #pragma unroll
            for (int ni=0;ni<8;ni++)
                #pragma unroll
                for (int j=0;j<4;j++) vmax = fmaxf(vmax, d[ni][j]);
        }
        // publish next tile's ac (disjoint buffer s^1; this tile reads only s)
        if (ct + 1 < NT && t < CTILE) ac[(s^1)*128 + t] = na;

        unsigned pend = 0xFFFFFFFFu;   // 8 ni x 4 j

        if (ct == 0){
            // direct-init: cols 0..39 (cb==0, ni<5) fill slots directly
            if (cb == 0){
                #pragma unroll
                for (int ni=0;ni<5;ni++){
                    #pragma unroll
                    for (int j=0;j<4;j++){
                        int col = ni*8 + qq*2 + (j&1);
                        int row = qb + g + ((j>>1)<<3);
                        ld[col*QTILE + row] = d[ni][j];
                        li[col*QTILE + row] = col;
                    }
                }
                pend &= ~0xFFFFFu;   // clear ni 0..4
            }
            __syncthreads();
            if (t < QTILE){
                vmin = 3.4e38f;
                #pragma unroll
                for (int j = 0; j < KNB; j++){
                    float lv = ld[j*QTILE + t];
                    if (lv < vmin){ vmin = lv; minpos = j; }
                }
                thr[t] = vmin;
            }
            __syncthreads();   // thr visible for the filter below
        }

        // ---- filter / insert retry loop (R12 control flow + vmax gate) ----
        for (;;){
            int of = 0;
            if (pend){
                const int r0w = qb + g;
                const float th0 = thr[r0w], th1 = thr[r0w + 8];
                if (vmax <= fminf(th0, th1)){
                    pend = 0;   // equivalent: every value fails its own threshold
                } else {
                    #pragma unroll
                    for (int ni=0;ni<8;ni++){
                        #pragma unroll
                        for (int j=0;j<4;j++){
                            const unsigned bit = 1u << (ni*4 + j);
                            if (!(pend & bit)) continue;
                            float v = d[ni][j];
                            int row = r0w + ((j>>1)<<3);
                            float th = (j>>1) ? th1 : th0;
                            if (v <= th){ pend &= ~bit; continue; }
                            int pos = atomicAdd(&cnt[row], 1);
                            if (pos < BCAP){
                                bufv[row*BPITCH + pos] = v;
                                bufi[row*BPITCH + pos] = c0 + cb + ni*8 + qq*2 + (j&1);
                                pend &= ~bit;
                            } else of = 1;
                        }
                    }
                }
            }
            int redo = __syncthreads_or(of);   // buf visible, redo known
            if (t < QTILE){
                int n = cnt[t]; if (n > BCAP) n = BCAP;
                for (int s2 = 0; s2 < n; s2++){
                    float v = bufv[t*BPITCH + s2];
                    if (v > vmin){
                        ld[minpos*QTILE + t] = v;
                        li[minpos*QTILE + t] = bufi[t*BPITCH + s2];
                        vmin = 3.4e38f;
                        #pragma unroll
                        for (int j = 0; j < KNB; j++){
                            float lv = ld[j*QTILE + t];
                            if (lv < vmin){ vmin = lv; minpos = j; }
                        }
                    }
                }
                cnt[t] = 0;
                thr[t] = vmin;
            }
            if (!redo) break;     // next tile's barrier 1 orders thr/cnt/buf
            __syncthreads();      // redo: updated thr visible for retry filter
        }
    }

    __syncthreads();   // final inserts visible
    if (t < QTILE){
        int* dst = g_idx + ((size_t)b*NN + q0 + t)*KNB;
        #pragma unroll
        for (int j = 0; j < KNB; j++) dst[j] = li[j*QTILE + t];
    }
}

// ---------------- K5: attention via gathered projections (warp / point) -----
__global__ void __launch_bounds__(256) k_attn(const float* __restrict__ x){
    __shared__ float es[8][160];
    __shared__ int   sidx[8][40];
    const int w    = threadIdx.x >> 5;
    const int lane = threadIdx.x & 31;
    const int pg   = blockIdx.x*8 + w;
    const int b    = pg >> 13, p = pg & (NN-1);
    const int* ip  = g_idx + (size_t)pg*KNB;
    sidx[w][lane] = ip[lane];
    if (lane < 8) sidx[w][lane+32] = ip[lane+32];
    const float* qrow = g_qp + (size_t)pg*CC;
    const float* kb   = g_kp + (size_t)b*NN*CC;
    const float* vb   = g_vp + (size_t)b*NN*CC;
    const float q0 = qrow[lane]    * 0.25f;
    const float q1 = qrow[lane+32] * 0.25f;
    const float kn0 = kb[(size_t)p*CC + lane];
    const float kn1 = kb[(size_t)p*CC + lane + 32];
    __syncwarp();
    const int hq = lane >> 4;
    for (int j = 0; j < KNB; j++){
        const float* kr = kb + (size_t)sidx[w][j]*CC;
        float p0 = q0*(kr[lane]    - kn0);
        float p1 = q1*(kr[lane+32] - kn1);
        #pragma unroll
        for (int o = 8; o; o >>= 1){
            p0 += __shfl_xor_sync(0xffffffffu, p0, o);
            p1 += __shfl_xor_sync(0xffffffffu, p1, o);
        }
        if ((lane & 15) == 0){
            es[w][hq*40 + j]     = p0;
            es[w][(2+hq)*40 + j] = p1;
        }
    }
    __syncwarp();
    if (lane < 4){
        float m = -3.4e38f;
        for (int j = 0; j < KNB; j++) m = fmaxf(m, es[w][lane*40+j]);
        float ssum = 0.f;
        for (int j = 0; j < KNB; j++){
            float e = __expf(es[w][lane*40+j] - m);
            es[w][lane*40+j] = e;
            ssum += e;
        }
        float inv = 1.f/ssum;
        for (int j = 0; j < KNB; j++) es[w][lane*40+j] *= inv;
    }
    __syncwarp();
    const float vn0 = vb[(size_t)p*CC + lane];
    const float vn1 = vb[(size_t)p*CC + lane + 32];
    float a0 = 0.f, a1 = 0.f;
    for (int j = 0; j < KNB; j++){
        const float* vr = vb + (size_t)sidx[w][j]*CC;
        a0 += es[w][hq*40+j]     * (vr[lane]    - vn0);
        a1 += es[w][(2+hq)*40+j] * (vr[lane+32] - vn1);
    }
    const float* xb = x + (size_t)b*CC*NN;
    g_y1[(size_t)pg*CC + lane]      = a0 + xb[(size_t)lane*NN + p];
    g_y1[(size_t)pg*CC + lane + 32] = a1 + xb[(size_t)(lane+32)*NN + p];
}

// ---------------- K6: BN stats (deterministic two-stage) ---------------------
__global__ void __launch_bounds__(256) k_stats(int srcsel, int which){
    __shared__ float ssum[256], ssq[256];
    const float* src = srcsel ? g_y2 : g_y1;
    const int t = threadIdx.x;
    const int c = t & 63, rl = t >> 6;
    const int r0 = blockIdx.x*512;
    float s = 0.f, s2 = 0.f;
    for (int r = rl; r < 512; r += 4){
        float v = src[(size_t)(r0+r)*CC + c];
        s += v; s2 += v*v;
    }
    ssum[t] = s; ssq[t] = s2;
    __syncthreads();
    if (t < 64){
        float a = ssum[t]+ssum[t+64]+ssum[t+128]+ssum[t+192];
        float q = ssq [t]+ssq [t+64]+ssq [t+128]+ssq [t+192];
        float* part = g_part + which*8192;
        part[blockIdx.x*128 + t]      = a;
        part[blockIdx.x*128 + 64 + t] = q;
    }
}

__global__ void k_bnfin(int which, const float* __restrict__ gamma,
                        const float* __restrict__ beta){
    const int c = threadIdx.x;
    const float* part = g_part + which*8192;
    float s = 0.f, s2 = 0.f;
    for (int blk = 0; blk < 64; blk++){
        s  += part[blk*128 + c];
        s2 += part[blk*128 + 64 + c];
    }
    const float inv = 1.f/(float)NPTS;
    float m = s*inv;
    float v = s2*inv - m*m;
    float sc = gamma[c]*rsqrtf(v + 1e-5f);
    g_scb[which*128 + c]      = sc;
    g_scb[which*128 + 64 + c] = beta[c] - m*sc;
}

// ---------------- K7: fused FFN (BN1-apply + W1/lrelu + W2 + residual) ------
#define FFN_SMEM ((64*68 + 64*260 + 256*68 + 256*68)*4)
__global__ void __launch_bounds__(256,1) k_ffn(const float* __restrict__ W1,
                                               const float* __restrict__ W2){
    extern __shared__ float s[];
    float* Xs  = s;
    float* W1t = Xs  + 64*68;
    float* Hs  = W1t + 64*260;
    float* W2t = Hs  + 256*68;
    __shared__ float sc1[64], bs1[64];
    const int t  = threadIdx.x;
    const int r0 = blockIdx.x*64;
    if (t < 64){ sc1[t] = g_scb[t]; bs1[t] = g_scb[64+t]; }
    for (int i = t; i < 256*64; i += 256){
        int o = i>>6, c = i&63;
        W1t[c*260 + o] = W1[i];
    }
    for (int i = t; i < 64*256; i += 256){
        int c = i>>8, o = i&255;
        W2t[o*68 + c] = W2[i];
    }
    __syncthreads();
    for (int i = t; i < 64*64; i += 256){
        int r = i>>6, c = i&63;
        Xs[c*68 + r] = g_y1[(size_t)(r0+r)*CC + c]*sc1[c] + bs1[c];
    }
    __syncthreads();
    {
        const int to = t >> 3, tr = t & 7;
        float acc[8][8];
        #pragma unroll
        for (int i=0;i<8;i++)
            #pragma unroll
            for (int j=0;j<8;j++) acc[i][j] = 0.f;
        #pragma unroll 4
        for (int k = 0; k < 64; k++){
            float4 a0 = *(const float4*)&Xs[k*68 + tr*8];
            float4 a1 = *(const float4*)&Xs[k*68 + tr*8 + 4];
            float4 w0 = *(const float4*)&W1t[k*260 + to*8];
            float4 w1 = *(const float4*)&W1t[k*260 + to*8 + 4];
            float av[8] = {a0.x,a0.y,a0.z,a0.w,a1.x,a1.y,a1.z,a1.w};
            float wv[8] = {w0.x,w0.y,w0.z,w0.w,w1.x,w1.y,w1.z,w1.w};
            #pragma unroll
            for (int oi=0;oi<8;oi++)
                #pragma unroll
                for (int ri=0;ri<8;ri++) acc[oi][ri] += wv[oi]*av[ri];
        }
        #pragma unroll
        for (int oi=0;oi<8;oi++)
            #pragma unroll
            for (int ri=0;ri<8;ri++){
                float h = acc[oi][ri];
                Hs[(to*8+oi)*68 + tr*8+ri] = (h > 0.f) ? h : 0.2f*h;
            }
    }
    __syncthreads();
    {
        const int tr2 = t & 15, tc2 = t >> 4;
        float acc[4][4];
        #pragma unroll
        for (int i=0;i<4;i++){ acc[i][0]=0.f; acc[i][1]=0.f; acc[i][2]=0.f; acc[i][3]=0.f; }
        #pragma unroll 8
        for (int o = 0; o < 256; o++){
            float4 h4 = *(const float4*)&Hs[o*68 + tr2*4];
            float4 w4 = *(const float4*)&W2t[o*68 + tc2*4];
            float hv[4] = {h4.x,h4.y,h4.z,h4.w};
            float wv[4] = {w4.x,w4.y,w4.z,w4.w};
            #pragma unroll
            for (int i=0;i<4;i++)
                #pragma unroll
                for (int j=0;j<4;j++) acc[i][j] += hv[i]*wv[j];
        }
        #pragma unroll
        for (int i = 0; i < 4; i++){
            int r = tr2*4 + i;
            float4 outv;
            outv.x = acc[i][0] + Xs[(tc2*4+0)*68 + r];
            outv.y = acc[i][1] + Xs[(tc2*4+1)*68 + r];
            outv.z = acc[i][2] + Xs[(tc2*4+2)*68 + r];
            outv.w = acc[i][3] + Xs[(tc2*4+3)*68 + r];
            *(float4*)&g_y2[(size_t)(r0+r)*CC + tc2*4] = outv;
        }
    }
}

// ---------------- K8: apply BN2 + transpose to (B,C,N) ----------------------
__global__ void __launch_bounds__(256) k_apply(float* __restrict__ out){
    __shared__ float tile[64][65];
    __shared__ float sc[64], bs[64];
    const int t = threadIdx.x;
    if (t < 64){ sc[t] = g_scb[128 + t]; bs[t] = g_scb[128 + 64 + t]; }
    const int n0 = blockIdx.x*64, b = blockIdx.y;
    __syncthreads();
    for (int i = t; i < 64*64; i += 256){
        int r = i>>6, c = i&63;
        tile[c][r] = g_y2[((size_t)b*NN + n0 + r)*CC + c]*sc[c] + bs[c];
    }
    __syncthreads();
    for (int i = t; i < 64*64; i += 256){
        int c = i>>6, n = i&63;
        out[((size_t)b*CC + c)*NN + n0 + n] = tile[c][n];
    }
}

// ---------------- launch -----------------------------------------------------
extern "C" void kernel_launch(void* const* d_in, const int* in_sizes, int n_in,
                              void* d_out, int out_size){
    const float* x  = (const float*)d_in[0];
    const float* Wq = (const float*)d_in[1];
    const float* Wk = (const float*)d_in[2];
    const float* Wv = (const float*)d_in[3];
    const float* W1 = (const float*)d_in[4];
    const float* W2 = (const float*)d_in[5];
    const float* g1 = (const float*)d_in[6];
    const float* b1 = (const float*)d_in[7];
    const float* g2 = (const float*)d_in[8];
    const float* b2 = (const float*)d_in[9];
    float* out = (float*)d_out;
    (void)in_sizes; (void)n_in; (void)out_size;

    cudaFuncSetAttribute(k_knn, cudaFuncAttributeMaxDynamicSharedMemorySize, KNN_SMEM);
    cudaFuncSetAttribute(k_ffn, cudaFuncAttributeMaxDynamicSharedMemorySize, FFN_SMEM);

    k_transpose<<<dim3(NN/32, CC/32, BB), dim3(32, 8)>>>(x);
    k_prep<<<NPTS/8, 256>>>();
    k_proj<<<NPTS/64, 256>>>(Wq, Wk, Wv);
    k_knn<<<dim3(NN/QTILE, BB), 256, KNN_SMEM>>>();   // 4th launch -> profiled
    k_attn<<<NPTS/8, 256>>>(x);
    k_stats<<<64, 256>>>(0, 0);
    k_bnfin<<<1, 64>>>(0, g1, b1);
    k_ffn<<<NPTS/64, 256, FFN_SMEM>>>(W1, W2);
    k_stats<<<64, 256>>>(1, 1);
    k_bnfin<<<1, 64>>>(1, g2, b2);
    k_apply<<<dim3(NN/64, BB), 256>>>(out);
}

// round 17
// speedup vs baseline: 1.0377x; 1.0377x over previous
#include <cuda_runtime.h>
#include <cuda_bf16.h>
#include <cstdint>

#define BB 4
#define CC 64
#define NN 8192
#define KNB 40
#define FFD 256
#define NPTS (BB*NN)
#define BCAP 32
#define BPITCH 33
#define CTILE 128
#define QTILE 64
#define GPITCH 72            // global row pitch for bf16 splits (144 bytes)

// ---------------- scratch (device globals: no allocations allowed) ----------
__device__ float g_pcd[NPTS*CC];   // (B,N,C) transposed input
__device__ __nv_bfloat16 g_pch[NPTS*GPITCH]; // bf16 hi split (144B pitched rows)
__device__ __nv_bfloat16 g_pcl[NPTS*GPITCH]; // bf16 lo split (144B pitched rows)
__device__ float g_aa [NPTS];      // squared norms
__device__ float g_qp [NPTS*CC];   // pcd @ Wq^T
__device__ float g_kp [NPTS*CC];   // pcd @ Wk^T
__device__ float g_vp [NPTS*CC];   // pcd @ Wv^T
__device__ int   g_idx[NPTS*KNB];  // knn indices
__device__ float g_y1 [NPTS*CC];
__device__ float g_y2 [NPTS*CC];
__device__ float g_part[2*64*128];
__device__ float g_scb [2*128];

__device__ __forceinline__ uint32_t sm_u32(const void* p){
    uint32_t a;
    asm("{ .reg .u64 t; cvta.to.shared.u64 t, %1; cvt.u32.u64 %0, t; }":"=r"(a):"l"(p));
    return a;
}
__device__ __forceinline__ void ldm_x4(uint32_t& r0, uint32_t& r1, uint32_t& r2,
                                       uint32_t& r3, uint32_t addr){
    asm volatile("ldmatrix.sync.aligned.m8n8.x4.shared.b16 {%0,%1,%2,%3}, [%4];"
        : "=r"(r0), "=r"(r1), "=r"(r2), "=r"(r3) : "r"(addr));
}
__device__ __forceinline__ void bulkcp(uint32_t dst, const void* src,
                                       uint32_t bytes, uint32_t mbar){
    asm volatile(
        "cp.async.bulk.shared::cluster.global.mbarrier::complete_tx::bytes "
        "[%0], [%1], %2, [%3];"
        :: "r"(dst), "l"(src), "r"(bytes), "r"(mbar) : "memory");
}
#define FENCE_ASYNC() asm volatile("fence.proxy.async.shared::cta;" ::: "memory")
#define MBAR_INIT(mbar, n) \
    asm volatile("mbarrier.init.shared.b64 [%0], %1;" :: "r"(mbar), "r"(n) : "memory")
#define MBAR_EXPECT(mbar, tx) \
    asm volatile("mbarrier.arrive.expect_tx.shared.b64 _, [%0], %1;" \
        :: "r"(mbar), "r"(tx) : "memory")
__device__ __forceinline__ void mbar_wait(uint32_t mbar, uint32_t phase){
    asm volatile(
        "{\n\t.reg .pred P1;\n\t"
        "WL%=:\n\t"
        "mbarrier.try_wait.parity.acquire.cta.shared::cta.b64 P1, [%0], %1, 0x989680;\n\t"
        "@P1 bra.uni WD%=;\n\t"
        "bra.uni WL%=;\n\t"
        "WD%=:\n\t}"
        :: "r"(mbar), "r"(phase) : "memory");
}

// ---------------- K1: transpose x (B,C,N) -> pcd (B,N,C) --------------------
__global__ void k_transpose(const float* __restrict__ x){
    __shared__ float t[32][33];
    const int n0 = blockIdx.x*32, c0 = blockIdx.y*32, b = blockIdx.z;
    const float* xb = x + (size_t)b*CC*NN;
    #pragma unroll
    for (int i = threadIdx.y; i < 32; i += 8)
        t[i][threadIdx.x] = xb[(size_t)(c0+i)*NN + n0 + threadIdx.x];
    __syncthreads();
    float* pb = g_pcd + (size_t)b*NN*CC;
    #pragma unroll
    for (int i = threadIdx.y; i < 32; i += 8)
        pb[(size_t)(n0+i)*CC + c0 + threadIdx.x] = t[threadIdx.x][i];
}

// ---------------- K2 (merged): aa + bf16 hi/lo split (warp per point) -------
__global__ void k_prep(){
    const int p    = blockIdx.x*8 + (threadIdx.x>>5);
    const int lane = threadIdx.x & 31;
    const float* r = g_pcd + (size_t)p*CC;
    float v0 = r[lane], v1 = r[lane+32];
    __nv_bfloat16 h0 = __float2bfloat16(v0), h1 = __float2bfloat16(v1);
    g_pch[(size_t)p*GPITCH + lane]      = h0;
    g_pch[(size_t)p*GPITCH + lane + 32] = h1;
    g_pcl[(size_t)p*GPITCH + lane]      = __float2bfloat16(v0 - __bfloat162float(h0));
    g_pcl[(size_t)p*GPITCH + lane + 32] = __float2bfloat16(v1 - __bfloat162float(h1));
    float a = v0*v0 + v1*v1;
    #pragma unroll
    for (int o = 16; o; o >>= 1) a += __shfl_xor_sync(0xffffffffu, a, o);
    if (!lane) g_aa[p] = a;
}

// ---------------- K3: qp/kp/vp = pcd @ W^T (64-pt tiles) ---------------------
__global__ void __launch_bounds__(256) k_proj(const float* __restrict__ Wq,
                                              const float* __restrict__ Wk,
                                              const float* __restrict__ Wv){
    __shared__ float Pt[64*68];   // [k][p]
    __shared__ float Wt[64*68];   // [k][o]
    const int t  = threadIdx.x;
    const int r0 = blockIdx.x*64;
    for (int i = t; i < 64*64; i += 256){
        int p = i>>6, k = i&63;
        Pt[k*68+p] = g_pcd[(size_t)(r0+p)*CC + k];
    }
    const int tp = t & 15, to = t >> 4;
    const float* Ws[3] = {Wq, Wk, Wv};
    float* Os[3];
    Os[0] = g_qp; Os[1] = g_kp; Os[2] = g_vp;
    for (int m = 0; m < 3; m++){
        __syncthreads();
        const float* W = Ws[m];
        for (int i = t; i < 64*64; i += 256){
            int o = i>>6, k = i&63;
            Wt[k*68+o] = W[i];
        }
        __syncthreads();
        float acc[4][4];
        #pragma unroll
        for (int i=0;i<4;i++) { acc[i][0]=0.f; acc[i][1]=0.f; acc[i][2]=0.f; acc[i][3]=0.f; }
        #pragma unroll 8
        for (int kk = 0; kk < 64; kk++){
            float4 a = *(const float4*)&Pt[kk*68 + tp*4];
            float4 w = *(const float4*)&Wt[kk*68 + to*4];
            float av[4] = {a.x,a.y,a.z,a.w};
            float wv[4] = {w.x,w.y,w.z,w.w};
            #pragma unroll
            for (int i=0;i<4;i++)
                #pragma unroll
                for (int j=0;j<4;j++) acc[i][j] += av[i]*wv[j];
        }
        float* O = Os[m];
        #pragma unroll
        for (int i = 0; i < 4; i++){
            float4 v4 = make_float4(acc[i][0], acc[i][1], acc[i][2], acc[i][3]);
            *(float4*)&O[(size_t)(r0 + tp*4 + i)*CC + to*4] = v4;
        }
    }
}

// ---------------- K4: KNN, mma.sync bf16-split + ldmatrix + cp.async.bulk ---
// smem bytes: Cbuf[2]@0 (each: CH 18432 + CL 18432) | fx@73728 | mbars
// Q is staged transiently in Cbuf[0] and hoisted to registers.
#define PITCHB 144            // 72 bf16 per row (smem == global pitch)
#define CB_OFF 0
#define CCOMP 18432           // one component (hi or lo) = 128 rows * 144 B
#define CBUF_SZ (2*CCOMP)
#define FX_OFF 73728
// fx floats: aq 64 | ac 256 | thr 64 | ld 2560 | bufv 2112 | li 2560 | bufi 2112 | cnt 64
#define BAR_OFF (FX_OFF + 9792*4)
#define KNN_SMEM (BAR_OFF + 16)

#define MMA_BF16(dd, a, b0_, b1_) \
    asm volatile("mma.sync.aligned.m16n8k16.row.col.f32.bf16.bf16.f32 " \
        "{%0,%1,%2,%3}, {%4,%5,%6,%7}, {%8,%9}, {%0,%1,%2,%3};" \
        : "+f"((dd)[0]), "+f"((dd)[1]), "+f"((dd)[2]), "+f"((dd)[3]) \
        : "r"((a)[0]), "r"((a)[1]), "r"((a)[2]), "r"((a)[3]), \
          "r"(b0_), "r"(b1_))

__global__ void __launch_bounds__(256,2) k_knn(){
    extern __shared__ char sm[];
    const uint32_t smb = sm_u32(sm);
    float* fx   = (float*)(sm + FX_OFF);
    float* aq   = fx;                  // 64
    float* ac   = fx + 64;             // 256 = 2 x 128
    float* thr  = fx + 320;            // 64
    float* ld   = fx + 384;            // 40*64
    float* bufv = fx + 2944;           // 64*33
    int*   li   = (int*)(fx + 5056);   // 40*64
    int*   bufi = (int*)(fx + 7616);   // 64*33
    int*   cnt  = (int*)(fx + 9728);   // 64
    const uint32_t bar0 = smb + BAR_OFF;
    const uint32_t bar1 = bar0 + 8;

    const int b  = blockIdx.y;
    const int q0 = blockIdx.x*QTILE;
    const int t  = threadIdx.x;
    const int lane = t & 31;
    const int g  = lane >> 2;          // group row 0..7
    const int qq = lane & 3;           // quad col 0..3
    const int qb = ((t>>5) & 3)*16;    // warp's query base
    const int cb = (t>>7)*64;          // warp's candidate-col base (0 or 64)

    const char* srcH = (const char*)g_pch + (size_t)(b*NN)*PITCHB;
    const char* srcL = (const char*)g_pcl + (size_t)(b*NN)*PITCHB;

    // ---- stage Q tiles transiently into Cbuf[0] (linear copy, same pitch) --
    {
        const uint4* qh = (const uint4*)(srcH + (size_t)q0*PITCHB);
        const uint4* ql = (const uint4*)(srcL + (size_t)q0*PITCHB);
        for (int i = t; i < 576; i += 256){          // 64 rows * 9 uint4
            *(uint4*)(sm + i*16) = qh[i];
            *(uint4*)(sm + 9216 + i*16) = ql[i];
        }
    }
    if (t < QTILE){ aq[t] = g_aa[(size_t)b*NN + q0 + t]; thr[t] = -3.4e38f; cnt[t] = 0; }
    if (t == 0){ MBAR_INIT(bar0, 1); MBAR_INIT(bar1, 1); }
    __syncthreads();   // Q staging + mbarrier init visible

    // ---- hoist Q fragments into registers (constant across all tiles) ----
    uint32_t ahr[4][4], alr[4][4];
    #pragma unroll
    for (int kc = 0; kc < 4; kc++){
        const int koff = kc*32 + qq*4;
        int r0b = (qb + g)*PITCHB + koff;
        int r1b = r0b + 8*PITCHB;
        ahr[kc][0] = *(const uint32_t*)(sm + r0b);
        ahr[kc][1] = *(const uint32_t*)(sm + r1b);
        ahr[kc][2] = *(const uint32_t*)(sm + r0b + 16);
        ahr[kc][3] = *(const uint32_t*)(sm + r1b + 16);
        alr[kc][0] = *(const uint32_t*)(sm + 9216 + r0b);
        alr[kc][1] = *(const uint32_t*)(sm + 9216 + r1b);
        alr[kc][2] = *(const uint32_t*)(sm + 9216 + r0b + 16);
        alr[kc][3] = *(const uint32_t*)(sm + 9216 + r1b + 16);
    }
    __syncthreads();   // all Q reads done before bulk copy overwrites Cbuf[0]

    // ---- bulk-copy prologue: tile 0 into buffer 0; ac[0] direct ----
    if (t == 0){
        FENCE_ASYNC();                 // order generic writes/reads -> async proxy
        MBAR_EXPECT(bar0, 2*CCOMP);
        bulkcp(smb + CB_OFF,         srcH, CCOMP, bar0);
        bulkcp(smb + CB_OFF + CCOMP, srcL, CCOMP, bar0);
    }
    if (t < CTILE) ac[t] = g_aa[(size_t)b*NN + t];

    // ---- per-lane ldmatrix base ----
    const int lm = lane >> 3;
    const uint32_t matOff = (uint32_t)((cb + (lm>>1)*8 + (lane&7))*PITCHB + (lm&1)*16);

    float vmin = -3.4e38f;   // owner state (t<64 owns query t)
    int   minpos = 0;
    uint32_t ph0 = 0, ph1 = 0;

    const int NT = NN/CTILE;   // 64
    for (int ct = 0; ct < NT; ct++){
        const int s = ct & 1;
        const int c0 = ct*CTILE;
        float na = 0.f;
        // ---- arm + issue next tile into other buffer (reads of s^1 finished
        //      before the prior or-barrier; fence orders them into async) ----
        if (ct + 1 < NT){
            if (t == 0){
                const uint32_t nbar = s ? bar0 : bar1;
                const uint32_t cbase = smb + CB_OFF + (uint32_t)(s^1)*CBUF_SZ;
                const size_t goff = (size_t)(ct+1)*CTILE*PITCHB;
                FENCE_ASYNC();
                MBAR_EXPECT(nbar, 2*CCOMP);
                bulkcp(cbase,         srcH + goff, CCOMP, nbar);
                bulkcp(cbase + CCOMP, srcL + goff, CCOMP, nbar);
            }
            if (t < CTILE) na = g_aa[(size_t)b*NN + (ct+1)*CTILE + t];
        }
        // ---- wait (acquire) for tile ct's data ----
        if (s == 0){ mbar_wait(bar0, ph0); ph0 ^= 1; }
        else       { mbar_wait(bar1, ph1); ph1 ^= 1; }
        __syncthreads();      // barrier 1: prior owner-phase state visible

        // ---- warp GEMM: 16q x 64c via m16n8k16 + ldmatrix, 3-term split ----
        const uint32_t chb = smb + CB_OFF + (uint32_t)s*CBUF_SZ + matOff;
        float d[8][4];
        #pragma unroll
        for (int ni=0;ni<8;ni++)
            #pragma unroll
            for (int j=0;j<4;j++) d[ni][j] = 0.f;

        #pragma unroll
        for (int kc = 0; kc < 4; kc++){
            const uint32_t ka = chb + kc*32;
            uint32_t bh[16], bl[16];
            #pragma unroll
            for (int grp = 0; grp < 4; grp++){
                ldm_x4(bh[grp*4], bh[grp*4+1], bh[grp*4+2], bh[grp*4+3],
                       ka + grp*16*PITCHB);
                ldm_x4(bl[grp*4], bl[grp*4+1], bl[grp*4+2], bl[grp*4+3],
                       ka + CCOMP + grp*16*PITCHB);
            }
            #pragma unroll
            for (int ni=0;ni<8;ni++){
                MMA_BF16(d[ni], ahr[kc], bh[ni*2], bh[ni*2+1]);
                MMA_BF16(d[ni], ahr[kc], bl[ni*2], bl[ni*2+1]);
                MMA_BF16(d[ni], alr[kc], bh[ni*2], bh[ni*2+1]);
            }
        }

        // ---- fold pd = 2*dot - aq - ac ----
        {
            const float* acb = ac + s*128;
            float aq0 = aq[qb + g];
            float aq1 = aq[qb + g + 8];
            #pragma unroll
            for (int ni=0;ni<8;ni++){
                float ac0 = acb[cb + ni*8 + qq*2];
                float ac1 = acb[cb + ni*8 + qq*2 + 1];
                d[ni][0] = 2.f*d[ni][0] - aq0 - ac0;
                d[ni][1] = 2.f*d[ni][1] - aq0 - ac1;
                d[ni][2] = 2.f*d[ni][2] - aq1 - ac0;
                d[ni][3] = 2.f*d[ni][3] - aq1 - ac1;
            }
        }
        // publish next tile's ac (disjoint buffer s^1; this tile reads only s)
        if (ct + 1 < NT && t < CTILE) ac[(s^1)*128 + t] = na;

        unsigned pend = 0xFFFFFFFFu;   // 8 ni x 4 j

        if (ct == 0){
            // direct-init: cols 0..39 (cb==0, ni<5) fill slots directly
            if (cb == 0){
                #pragma unroll
                for (int ni=0;ni<5;ni++){
                    #pragma unroll
                    for (int j=0;j<4;j++){
                        int col = ni*8 + qq*2 + (j&1);
                        int row = qb + g + ((j>>1)<<3);
                        ld[col*QTILE + row] = d[ni][j];
                        li[col*QTILE + row] = col;
                    }
                }
                pend &= ~0xFFFFFu;   // clear ni 0..4
            }
            __syncthreads();
            if (t < QTILE){
                vmin = 3.4e38f;
                #pragma unroll
                for (int j = 0; j < KNB; j++){
                    float lv = ld[j*QTILE + t];
                    if (lv < vmin){ vmin = lv; minpos = j; }
                }
                thr[t] = vmin;
            }
            __syncthreads();   // thr visible for the filter below
        }

        // ---- filter / insert retry loop (R14-proven structure) ----
        for (;;){
            int of = 0;
            if (pend){
                const int r0w = qb + g;
                const float th0 = thr[r0w], th1 = thr[r0w + 8];
                #pragma unroll
                for (int ni=0;ni<8;ni++){
                    #pragma unroll
                    for (int j=0;j<4;j++){
                        const unsigned bit = 1u << (ni*4 + j);
                        if (!(pend & bit)) continue;
                        float v = d[ni][j];
                        int row = r0w + ((j>>1)<<3);
                        float th = (j>>1) ? th1 : th0;
                        if (v <= th){ pend &= ~bit; continue; }
                        int pos = atomicAdd(&cnt[row], 1);
                        if (pos < BCAP){
                            bufv[row*BPITCH + pos] = v;
                            bufi[row*BPITCH + pos] = c0 + cb + ni*8 + qq*2 + (j&1);
                            pend &= ~bit;
                        } else of = 1;
                    }
                }
            }
            int redo = __syncthreads_or(of);   // buf visible, redo known
            if (t < QTILE){
                int n = cnt[t]; if (n > BCAP) n = BCAP;
                for (int s2 = 0; s2 < n; s2++){
                    float v = bufv[t*BPITCH + s2];
                    if (v > vmin){
                        ld[minpos*QTILE + t] = v;
                        li[minpos*QTILE + t] = bufi[t*BPITCH + s2];
                        vmin = 3.4e38f;
                        #pragma unroll
                        for (int j = 0; j < KNB; j++){
                            float lv = ld[j*QTILE + t];
                            if (lv < vmin){ vmin = lv; minpos = j; }
                        }
                    }
                }
                cnt[t] = 0;
                thr[t] = vmin;
            }
            if (!redo) break;     // next tile's barrier 1 orders thr/cnt/buf
            __syncthreads();      // redo: updated thr visible for retry filter
        }
    }

    __syncthreads();   // final inserts visible
    if (t < QTILE){
        int* dst = g_idx + ((size_t)b*NN + q0 + t)*KNB;
        #pragma unroll
        for (int j = 0; j < KNB; j++) dst[j] = li[j*QTILE + t];
    }
}

// ---------------- K5: attention via gathered projections (warp / point) -----
__global__ void __launch_bounds__(256) k_attn(const float* __restrict__ x){
    __shared__ float es[8][160];
    __shared__ int   sidx[8][40];
    const int w    = threadIdx.x >> 5;
    const int lane = threadIdx.x & 31;
    const int pg   = blockIdx.x*8 + w;
    const int b    = pg >> 13, p = pg & (NN-1);
    const int* ip  = g_idx + (size_t)pg*KNB;
    sidx[w][lane] = ip[lane];
    if (lane < 8) sidx[w][lane+32] = ip[lane+32];
    const float* qrow = g_qp + (size_t)pg*CC;
    const float* kb   = g_kp + (size_t)b*NN*CC;
    const float* vb   = g_vp + (size_t)b*NN*CC;
    const float q0 = qrow[lane]    * 0.25f;
    const float q1 = qrow[lane+32] * 0.25f;
    const float kn0 = kb[(size_t)p*CC + lane];
    const float kn1 = kb[(size_t)p*CC + lane + 32];
    __syncwarp();
    const int hq = lane >> 4;
    for (int j = 0; j < KNB; j++){
        const float* kr = kb + (size_t)sidx[w][j]*CC;
        float p0 = q0*(kr[lane]    - kn0);
        float p1 = q1*(kr[lane+32] - kn1);
        #pragma unroll
        for (int o = 8; o; o >>= 1){
            p0 += __shfl_xor_sync(0xffffffffu, p0, o);
            p1 += __shfl_xor_sync(0xffffffffu, p1, o);
        }
        if ((lane & 15) == 0){
            es[w][hq*40 + j]     = p0;
            es[w][(2+hq)*40 + j] = p1;
        }
    }
    __syncwarp();
    if (lane < 4){
        float m = -3.4e38f;
        for (int j = 0; j < KNB; j++) m = fmaxf(m, es[w][lane*40+j]);
        float ssum = 0.f;
        for (int j = 0; j < KNB; j++){
            float e = __expf(es[w][lane*40+j] - m);
            es[w][lane*40+j] = e;
            ssum += e;
        }
        float inv = 1.f/ssum;
        for (int j = 0; j < KNB; j++) es[w][lane*40+j] *= inv;
    }
    __syncwarp();
    const float vn0 = vb[(size_t)p*CC + lane];
    const float vn1 = vb[(size_t)p*CC + lane + 32];
    float a0 = 0.f, a1 = 0.f;
    for (int j = 0; j < KNB; j++){
        const float* vr = vb + (size_t)sidx[w][j]*CC;
        a0 += es[w][hq*40+j]     * (vr[lane]    - vn0);
        a1 += es[w][(2+hq)*40+j] * (vr[lane+32] - vn1);
    }
    const float* xb = x + (size_t)b*CC*NN;
    g_y1[(size_t)pg*CC + lane]      = a0 + xb[(size_t)lane*NN + p];
    g_y1[(size_t)pg*CC + lane + 32] = a1 + xb[(size_t)(lane+32)*NN + p];
}

// ---------------- K6: BN stats (deterministic two-stage) ---------------------
__global__ void __launch_bounds__(256) k_stats(int srcsel, int which){
    __shared__ float ssum[256], ssq[256];
    const float* src = srcsel ? g_y2 : g_y1;
    const int t = threadIdx.x;
    const int c = t & 63, rl = t >> 6;
    const int r0 = blockIdx.x*512;
    float s = 0.f, s2 = 0.f;
    for (int r = rl; r < 512; r += 4){
        float v = src[(size_t)(r0+r)*CC + c];
        s += v; s2 += v*v;
    }
    ssum[t] = s; ssq[t] = s2;
    __syncthreads();
    if (t < 64){
        float a = ssum[t]+ssum[t+64]+ssum[t+128]+ssum[t+192];
        float q = ssq [t]+ssq [t+64]+ssq [t+128]+ssq [t+192];
        float* part = g_part + which*8192;
        part[blockIdx.x*128 + t]      = a;
        part[blockIdx.x*128 + 64 + t] = q;
    }
}

__global__ void k_bnfin(int which, const float* __restrict__ gamma,
                        const float* __restrict__ beta){
    const int c = threadIdx.x;
    const float* part = g_part + which*8192;
    float s = 0.f, s2 = 0.f;
    for (int blk = 0; blk < 64; blk++){
        s  += part[blk*128 + c];
        s2 += part[blk*128 + 64 + c];
    }
    const float inv = 1.f/(float)NPTS;
    float m = s*inv;
    float v = s2*inv - m*m;
    float sc = gamma[c]*rsqrtf(v + 1e-5f);
    g_scb[which*128 + c]      = sc;
    g_scb[which*128 + 64 + c] = beta[c] - m*sc;
}

// ---------------- K7: fused FFN (BN1-apply + W1/lrelu + W2 + residual) ------
#define FFN_SMEM ((64*68 + 64*260 + 256*68 + 256*68)*4)
__global__ void __launch_bounds__(256,1) k_ffn(const float* __restrict__ W1,
                                               const float* __restrict__ W2){
    extern __shared__ float s[];
    float* Xs  = s;
    float* W1t = Xs  + 64*68;
    float* Hs  = W1t + 64*260;
    float* W2t = Hs  + 256*68;
    __shared__ float sc1[64], bs1[64];
    const int t  = threadIdx.x;
    const int r0 = blockIdx.x*64;
    if (t < 64){ sc1[t] = g_scb[t]; bs1[t] = g_scb[64+t]; }
    for (int i = t; i < 256*64; i += 256){
        int o = i>>6, c = i&63;
        W1t[c*260 + o] = W1[i];
    }
    for (int i = t; i < 64*256; i += 256){
        int c = i>>8, o = i&255;
        W2t[o*68 + c] = W2[i];
    }
    __syncthreads();
    for (int i = t; i < 64*64; i += 256){
        int r = i>>6, c = i&63;
        Xs[c*68 + r] = g_y1[(size_t)(r0+r)*CC + c]*sc1[c] + bs1[c];
    }
    __syncthreads();
    {
        const int to = t >> 3, tr = t & 7;
        float acc[8][8];
        #pragma unroll
        for (int i=0;i<8;i++)
            #pragma unroll
            for (int j=0;j<8;j++) acc[i][j] = 0.f;
        #pragma unroll 4
        for (int k = 0; k < 64; k++){
            float4 a0 = *(const float4*)&Xs[k*68 + tr*8];
            float4 a1 = *(const float4*)&Xs[k*68 + tr*8 + 4];
            float4 w0 = *(const float4*)&W1t[k*260 + to*8];
            float4 w1 = *(const float4*)&W1t[k*260 + to*8 + 4];
            float av[8] = {a0.x,a0.y,a0.z,a0.w,a1.x,a1.y,a1.z,a1.w};
            float wv[8] = {w0.x,w0.y,w0.z,w0.w,w1.x,w1.y,w1.z,w1.w};
            #pragma unroll
            for (int oi=0;oi<8;oi++)
                #pragma unroll
                for (int ri=0;ri<8;ri++) acc[oi][ri] += wv[oi]*av[ri];
        }
        #pragma unroll
        for (int oi=0;oi<8;oi++)
            #pragma unroll
            for (int ri=0;ri<8;ri++){
                float h = acc[oi][ri];
                Hs[(to*8+oi)*68 + tr*8+ri] = (h > 0.f) ? h : 0.2f*h;
            }
    }
    __syncthreads();
    {
        const int tr2 = t & 15, tc2 = t >> 4;
        float acc[4][4];
        #pragma unroll
        for (int i=0;i<4;i++){ acc[i][0]=0.f; acc[i][1]=0.f; acc[i][2]=0.f; acc[i][3]=0.f; }
        #pragma unroll 8
        for (int o = 0; o < 256; o++){
            float4 h4 = *(const float4*)&Hs[o*68 + tr2*4];
            float4 w4 = *(const float4*)&W2t[o*68 + tc2*4];
            float hv[4] = {h4.x,h4.y,h4.z,h4.w};
            float wv[4] = {w4.x,w4.y,w4.z,w4.w};
            #pragma unroll
            for (int i=0;i<4;i++)
                #pragma unroll
                for (int j=0;j<4;j++) acc[i][j] += hv[i]*wv[j];
        }
        #pragma unroll
        for (int i = 0; i < 4; i++){
            int r = tr2*4 + i;
            float4 outv;
            outv.x = acc[i][0] + Xs[(tc2*4+0)*68 + r];
            outv.y = acc[i][1] + Xs[(tc2*4+1)*68 + r];
            outv.z = acc[i][2] + Xs[(tc2*4+2)*68 + r];
            outv.w = acc[i][3] + Xs[(tc2*4+3)*68 + r];
            *(float4*)&g_y2[(size_t)(r0+r)*CC + tc2*4] = outv;
        }
    }
}

// ---------------- K8: apply BN2 + transpose to (B,C,N) ----------------------
__global__ void __launch_bounds__(256) k_apply(float* __restrict__ out){
    __shared__ float tile[64][65];
    __shared__ float sc[64], bs[64];
    const int t = threadIdx.x;
    if (t < 64){ sc[t] = g_scb[128 + t]; bs[t] = g_scb[128 + 64 + t]; }
    const int n0 = blockIdx.x*64, b = blockIdx.y;
    __syncthreads();
    for (int i = t; i < 64*64; i += 256){
        int r = i>>6, c = i&63;
        tile[c][r] = g_y2[((size_t)b*NN + n0 + r)*CC + c]*sc[c] + bs[c];
    }
    __syncthreads();
    for (int i = t; i < 64*64; i += 256){
        int c = i>>6, n = i&63;
        out[((size_t)b*CC + c)*NN + n0 + n] = tile[c][n];
    }
}

// ---------------- launch -----------------------------------------------------
extern "C" void kernel_launch(void* const* d_in, const int* in_sizes, int n_in,
                              void* d_out, int out_size){
    const float* x  = (const float*)d_in[0];
    const float* Wq = (const float*)d_in[1];
    const float* Wk = (const float*)d_in[2];
    const float* Wv = (const float*)d_in[3];
    const float* W1 = (const float*)d_in[4];
    const float* W2 = (const float*)d_in[5];
    const float* g1 = (const float*)d_in[6];
    const float* b1 = (const float*)d_in[7];
    const float* g2 = (const float*)d_in[8];
    const float* b2 = (const float*)d_in[9];
    float* out = (float*)d_out;
    (void)in_sizes; (void)n_in; (void)out_size;

    cudaFuncSetAttribute(k_knn, cudaFuncAttributeMaxDynamicSharedMemorySize, KNN_SMEM);
    cudaFuncSetAttribute(k_ffn, cudaFuncAttributeMaxDynamicSharedMemorySize, FFN_SMEM);

    k_transpose<<<dim3(NN/32, CC/32, BB), dim3(32, 8)>>>(x);
    k_prep<<<NPTS/8, 256>>>();
    k_proj<<<NPTS/64, 256>>>(Wq, Wk, Wv);
    k_knn<<<dim3(NN/QTILE, BB), 256, KNN_SMEM>>>();   // 4th launch -> profiled
    k_attn<<<NPTS/8, 256>>>(x);
    k_stats<<<64, 256>>>(0, 0);
    k_bnfin<<<1, 64>>>(0, g1, b1);
    k_ffn<<<NPTS/64, 256, FFN_SMEM>>>(W1, W2);
    k_stats<<<64, 256>>>(1, 1);
    k_bnfin<<<1, 64>>>(1, g2, b2);
    k_apply<<<dim3(NN/64, BB), 256>>>(out);
}